// round 12
// baseline (speedup 1.0000x reference)
#include <cuda_runtime.h>
#include <cuda_bf16.h>
#include <math.h>
#include <stdint.h>

#define HW    65536
#define IMG   256
#define BATCH 4
#define CH    192
#define HEADS 8
#define HD    24
#define KDIM  192
#define KP    96      // k pairs
#define KITER 6       // K=32 chunks

// ---------------- scratch (device globals; no runtime allocation) ----------------
__device__ float    g_qkv [(long)BATCH * 576 * HW];   // after 1x1 conv (fp32)
__device__ __nv_bfloat16 g_qkh[(long)BATCH * 384 * HW];  // q,k after dw, bf16 hi
__device__ __nv_bfloat16 g_qkl[(long)BATCH * 384 * HW];  // q,k after dw, bf16 lo
__device__ uint32_t g_xphi[(long)BATCH * KP * HW];    // x packed bf16 k-pairs, hi
__device__ uint32_t g_xplo[(long)BATCH * KP * HW];    // lo
__device__ uint32_t g_vphi[(long)BATCH * KP * HW];    // v packed bf16 k-pairs, hi
__device__ uint32_t g_vplo[(long)BATCH * KP * HW];
__device__ __nv_bfloat16 g_awhi[576 * KDIM];          // qkv_w bf16 hi
__device__ __nv_bfloat16 g_awlo[576 * KDIM];
__device__ __nv_bfloat16 g_wbhi[BATCH * CH * KDIM];   // folded proj W bf16 hi
__device__ __nv_bfloat16 g_wblo[BATCH * CH * KDIM];
__device__ float g_S  [BATCH * HEADS * HD * HD];
__device__ float g_ssq[2 * BATCH * HEADS * HD];

// ---------------- helpers ---------------------------------------------------------
__device__ __forceinline__ void split1(float v, __nv_bfloat16& h, __nv_bfloat16& l)
{
    h = __float2bfloat16(v);
    l = __float2bfloat16(v - __bfloat162float(h));
}
__device__ __forceinline__ uint32_t smem_u32(const void* p)
{
    uint32_t a;
    asm("{ .reg .u64 t; cvta.to.shared.u64 t, %1; cvt.u32.u64 %0, t; }" : "=r"(a) : "l"(p));
    return a;
}
__device__ __forceinline__ void mma_bf16(float* d, const uint32_t* a, const uint32_t* b)
{
    asm volatile(
        "mma.sync.aligned.m16n8k16.row.col.f32.bf16.bf16.f32 "
        "{%0,%1,%2,%3}, {%4,%5,%6,%7}, {%8,%9}, {%0,%1,%2,%3};\n"
        : "+f"(d[0]), "+f"(d[1]), "+f"(d[2]), "+f"(d[3])
        : "r"(a[0]), "r"(a[1]), "r"(a[2]), "r"(a[3]), "r"(b[0]), "r"(b[1]));
}
__device__ __forceinline__ void ldsm_x4(uint32_t* r, uint32_t addr)
{
    asm volatile("ldmatrix.sync.aligned.m8n8.x4.shared.b16 {%0,%1,%2,%3}, [%4];"
                 : "=r"(r[0]), "=r"(r[1]), "=r"(r[2]), "=r"(r[3]) : "r"(addr));
}
__device__ __forceinline__ void ldsm_x2(uint32_t* r, uint32_t addr)
{
    asm volatile("ldmatrix.sync.aligned.m8n8.x2.shared.b16 {%0,%1}, [%2];"
                 : "=r"(r[0]), "=r"(r[1]) : "r"(addr));
}
#define CP_ASYNC16(saddr, gptr) \
    asm volatile("cp.async.cg.shared.global [%0], [%1], 16;" :: "r"(saddr), "l"(gptr))
#define CP_COMMIT()  asm volatile("cp.async.commit_group;" ::: "memory")
#define CP_WAIT0()   asm volatile("cp.async.wait_group 0;" ::: "memory")
#define CP_WAIT1()   asm volatile("cp.async.wait_group 1;" ::: "memory")

// main GEMM smem (u32 units)
#define A_PLANE(st, p) (((st) * 2 + (p)) * 64 * 20)
#define B_PLANE(st, p) (7680 + ((st) * 2 + (p)) * 16 * 136)
#define SMEM_DYN_BYTES ((7680 + 3 * 2 * 16 * 136) * 4)   // 82944 B

// gram smem (u32 units)
#define GQH 0
#define GQL 2176
#define GKH 4352
#define GKL 5984
#define GSTG 7616
#define GSM_BYTES (2 * GSTG * 4)   // 60928 B

// ---------------- zero accumulators ----------------------------------------------
__global__ void zero_kernel()
{
    int i = blockIdx.x * blockDim.x + threadIdx.x;
    if (i < BATCH * HEADS * HD * HD) g_S[i] = 0.f;
    if (i < 2 * BATCH * HEADS * HD)  g_ssq[i] = 0.f;
}

// ---------------- split x -> packed bf16 k-pair planes ----------------------------
__global__ __launch_bounds__(256) void split_x_kernel(const float* __restrict__ x)
{
    const int n = (blockIdx.x * 256 + threadIdx.x) * 4;
    const int j = blockIdx.y;
    const int b = blockIdx.z;
    const float* r0 = x + ((long)b * KDIM + 2 * j) * HW + n;
    float4 v0 = *reinterpret_cast<const float4*>(r0);
    float4 v1 = *reinterpret_cast<const float4*>(r0 + HW);
    float e[4] = {v0.x, v0.y, v0.z, v0.w};
    float o[4] = {v1.x, v1.y, v1.z, v1.w};
    uint4 hi, lo;
    uint32_t* hp = &hi.x; uint32_t* lp = &lo.x;
#pragma unroll
    for (int i = 0; i < 4; i++) {
        __nv_bfloat16 eh, el, oh, ol;
        split1(e[i], eh, el);
        split1(o[i], oh, ol);
        hp[i] = (uint32_t)*reinterpret_cast<unsigned short*>(&eh) |
                ((uint32_t)*reinterpret_cast<unsigned short*>(&oh) << 16);
        lp[i] = (uint32_t)*reinterpret_cast<unsigned short*>(&el) |
                ((uint32_t)*reinterpret_cast<unsigned short*>(&ol) << 16);
    }
    const long w = ((long)b * KP + j) * HW + n;
    *reinterpret_cast<uint4*>(&g_xphi[w]) = hi;
    *reinterpret_cast<uint4*>(&g_xplo[w]) = lo;
}

// ---------------- split qkv_w -> bf16 hi/lo planes --------------------------------
__global__ void split_aw_kernel(const float* __restrict__ qkv_w)
{
    int i = blockIdx.x * 256 + threadIdx.x;
    if (i < 576 * KDIM) {
        __nv_bfloat16 h, l;
        split1(qkv_w[i], h, l);
        g_awhi[i] = h; g_awlo[i] = l;
    }
}

// ---------------- bf16 split GEMM (unchanged) -------------------------------------
__global__ __launch_bounds__(256) void bf16_gemm_kernel(
    const __nv_bfloat16* __restrict__ Ahi, const __nv_bfloat16* __restrict__ Alo, long aStride,
    const uint32_t* __restrict__ Bhi, const uint32_t* __restrict__ Blo,
    float* __restrict__ C, long cStride, int M)
{
    extern __shared__ uint32_t sm[];
    const uint32_t smb = smem_u32(sm);

    const int tid  = threadIdx.x;
    const int lane = tid & 31;
    const int wid  = tid >> 5;
    const int bm   = blockIdx.x * 64;
    const long n0  = (long)blockIdx.y * 128;
    const int bz   = blockIdx.z;

    const __nv_bfloat16* Ah = Ahi + (long)bz * aStride;
    const __nv_bfloat16* Al = Alo + (long)bz * aStride;
    const uint32_t* Bh = Bhi + (long)bz * KP * HW;
    const uint32_t* Bl = Blo + (long)bz * KP * HW;
    float* Cb = C + (long)bz * cStride;

    const int warp_m = (wid & 1) * 32;
    const int warp_n = (wid >> 1) * 32;
    const int r  = lane >> 2;
    const int cq = lane & 3;
    const int lrow = lane & 15;
    const int lcol = (lane >> 4) * 4;

    float acc[2][4][4];
#pragma unroll
    for (int mt = 0; mt < 2; mt++)
#pragma unroll
        for (int nt = 0; nt < 4; nt++)
#pragma unroll
            for (int i = 0; i < 4; i++) acc[mt][nt][i] = 0.f;

    auto load_chunk = [&](int c, int st) {
        {
            int m = tid >> 2, kg = tid & 3;
            long ge = (long)(bm + m) * KDIM + c * 32 + kg * 8;
            CP_ASYNC16(smb + (A_PLANE(st, 0) + m * 20 + kg * 4) * 4, (const char*)Ah + ge * 2);
            CP_ASYNC16(smb + (A_PLANE(st, 1) + m * 20 + kg * 4) * 4, (const char*)Al + ge * 2);
        }
#pragma unroll
        for (int i = 0; i < 2; i++) {
            int slot = tid + i * 256;
            int j = slot >> 5, ln = slot & 31;
            long gw = ((long)(c * 16 + j)) * HW + n0 + 4 * ln;
            CP_ASYNC16(smb + (B_PLANE(st, 0) + j * 136 + 4 * ln) * 4, Bh + gw);
            CP_ASYNC16(smb + (B_PLANE(st, 1) + j * 136 + 4 * ln) * 4, Bl + gw);
        }
    };

    load_chunk(0, 0); CP_COMMIT();
    load_chunk(1, 1); CP_COMMIT();

    for (int c = 0; c < KITER; c++) {
        const int st = c % 3;
        if (c == KITER - 1) { CP_WAIT0(); } else { CP_WAIT1(); }
        __syncthreads();

        const uint32_t baseHi = smb + A_PLANE(st, 0) * 4;
        const uint32_t baseLo = smb + A_PLANE(st, 1) * 4;
        const uint32_t* BsH = sm + B_PLANE(st, 0);
        const uint32_t* BsL = sm + B_PLANE(st, 1);

#pragma unroll
        for (int ksub = 0; ksub < 2; ksub++) {
            uint32_t ah[2][4], al[2][4], bh[4][2], bl[4][2];
#pragma unroll
            for (int mt = 0; mt < 2; mt++) {
                const uint32_t roff = ((warp_m + mt * 16 + lrow) * 20 + lcol + ksub * 8) * 4;
                ldsm_x4(ah[mt], baseHi + roff);
                ldsm_x4(al[mt], baseLo + roff);
            }
            const int kp0 = ksub * 8;
#pragma unroll
            for (int nt = 0; nt < 4; nt++) {
                const int n = warp_n + nt * 8 + r;
                bh[nt][0] = BsH[(kp0 + cq) * 136 + n];
                bh[nt][1] = BsH[(kp0 + cq + 4) * 136 + n];
                bl[nt][0] = BsL[(kp0 + cq) * 136 + n];
                bl[nt][1] = BsL[(kp0 + cq + 4) * 136 + n];
            }

            if (ksub == 0 && c + 2 < KITER) {
                load_chunk(c + 2, (c + 2) % 3);
                CP_COMMIT();
            }

#pragma unroll
            for (int mt = 0; mt < 2; mt++)
#pragma unroll
                for (int nt = 0; nt < 4; nt++)
                    mma_bf16(acc[mt][nt], ah[mt], bh[nt]);
#pragma unroll
            for (int mt = 0; mt < 2; mt++)
#pragma unroll
                for (int nt = 0; nt < 4; nt++)
                    mma_bf16(acc[mt][nt], ah[mt], bl[nt]);
#pragma unroll
            for (int mt = 0; mt < 2; mt++)
#pragma unroll
                for (int nt = 0; nt < 4; nt++)
                    mma_bf16(acc[mt][nt], al[mt], bh[nt]);
        }
    }

#pragma unroll
    for (int mt = 0; mt < 2; mt++)
#pragma unroll
        for (int nt = 0; nt < 4; nt++) {
            const int row = bm + warp_m + mt * 16 + r;
            const long col = n0 + warp_n + nt * 8 + 2 * cq;
            *reinterpret_cast<float2*>(Cb + (long)row * HW + col) =
                make_float2(acc[mt][nt][0], acc[mt][nt][1]);
            *reinterpret_cast<float2*>(Cb + (long)(row + 8) * HW + col) =
                make_float2(acc[mt][nt][2], acc[mt][nt][3]);
        }
}

// ---------------- depthwise 3x3: q,k -> bf16 hi/lo (+sumsq); v -> packed pairs ----
__global__ __launch_bounds__(256) void dwconv_kernel(const float* __restrict__ in,
                                                     const float* __restrict__ w)
{
    const int y = blockIdx.y;     // 0..383 single q/k channel; 384..479 v pair
    const int b = blockIdx.z;
    const int t = threadIdx.x;
    const int r0 = blockIdx.x * 8;

    __shared__ float s[10][258];

    if (y < 384) {
        const int ch = y;
        const float* ip = in + ((long)b * 576 + ch) * HW;
        __nv_bfloat16* oh = g_qkh + ((long)b * 384 + ch) * HW;
        __nv_bfloat16* ol = g_qkl + ((long)b * 384 + ch) * HW;
        float w9[9];
#pragma unroll
        for (int i = 0; i < 9; i++) w9[i] = __ldg(&w[ch * 9 + i]);
#pragma unroll
        for (int rr = 0; rr < 10; rr++) {
            int rw = r0 - 1 + rr;
            s[rr][t + 1] = (rw >= 0 && rw < IMG) ? ip[rw * IMG + t] : 0.f;
        }
        if (t < 10) { s[t][0] = 0.f; s[t][257] = 0.f; }
        __syncthreads();
        float sq = 0.f;
#pragma unroll
        for (int rr = 0; rr < 8; rr++) {
            float a = 0.f;
#pragma unroll
            for (int ky = 0; ky < 3; ky++)
#pragma unroll
                for (int kx = 0; kx < 3; kx++)
                    a += s[rr + ky][t + kx] * w9[ky * 3 + kx];
            __nv_bfloat16 hh, ll;
            split1(a, hh, ll);
            oh[(r0 + rr) * IMG + t] = hh;
            ol[(r0 + rr) * IMG + t] = ll;
            sq += a * a;
        }
        __shared__ float wsum[8];
#pragma unroll
        for (int off = 16; off > 0; off >>= 1)
            sq += __shfl_xor_sync(0xFFFFFFFFu, sq, off);
        if ((t & 31) == 0) wsum[t >> 5] = sq;
        __syncthreads();
        if (t == 0) {
            float ssum = 0.f;
#pragma unroll
            for (int i = 0; i < 8; i++) ssum += wsum[i];
            int off = (ch < CH) ? (b * CH + ch)
                                : (BATCH * HEADS * HD + b * CH + (ch - CH));
            atomicAdd(&g_ssq[off], ssum);
        }
    } else {
        const int p = y - 384;             // v channel pair
        const int ch0 = 384 + 2 * p;
        float ce[8], co[8];
#pragma unroll
        for (int cc = 0; cc < 2; cc++) {
            const int ch = ch0 + cc;
            const float* ip = in + ((long)b * 576 + ch) * HW;
            float w9[9];
#pragma unroll
            for (int i = 0; i < 9; i++) w9[i] = __ldg(&w[ch * 9 + i]);
            __syncthreads();
#pragma unroll
            for (int rr = 0; rr < 10; rr++) {
                int rw = r0 - 1 + rr;
                s[rr][t + 1] = (rw >= 0 && rw < IMG) ? ip[rw * IMG + t] : 0.f;
            }
            if (t < 10) { s[t][0] = 0.f; s[t][257] = 0.f; }
            __syncthreads();
            float* dst = cc ? co : ce;
#pragma unroll
            for (int rr = 0; rr < 8; rr++) {
                float a = 0.f;
#pragma unroll
                for (int ky = 0; ky < 3; ky++)
#pragma unroll
                    for (int kx = 0; kx < 3; kx++)
                        a += s[rr + ky][t + kx] * w9[ky * 3 + kx];
                dst[rr] = a;
            }
        }
        const long vbase = ((long)b * KP + p) * HW;
#pragma unroll
        for (int rr = 0; rr < 8; rr++) {
            __nv_bfloat16 eh, el, oh2, ol2;
            split1(ce[rr], eh, el);
            split1(co[rr], oh2, ol2);
            uint32_t hw_ = (uint32_t)*reinterpret_cast<unsigned short*>(&eh) |
                           ((uint32_t)*reinterpret_cast<unsigned short*>(&oh2) << 16);
            uint32_t lw_ = (uint32_t)*reinterpret_cast<unsigned short*>(&el) |
                           ((uint32_t)*reinterpret_cast<unsigned short*>(&ol2) << 16);
            g_vphi[vbase + (r0 + rr) * IMG + t] = hw_;
            g_vplo[vbase + (r0 + rr) * IMG + t] = lw_;
        }
    }
}

// ---------------- gram via tensor cores: S[24x24] = q k^T per (b,h) --------------
__global__ __launch_bounds__(256) void qk_gram_kernel()
{
    extern __shared__ uint32_t gsm[];
    const int tid = threadIdx.x, lane = tid & 31, wid = tid >> 5;
    const int b = blockIdx.z, h = blockIdx.y;
    const int bh = b * HEADS + h;
    const long px0 = (long)blockIdx.x * 2048;
    const __nv_bfloat16* QH = g_qkh + ((long)b * 384 + h * HD) * HW;
    const __nv_bfloat16* QL = g_qkl + ((long)b * 384 + h * HD) * HW;
    const __nv_bfloat16* KH = g_qkh + ((long)b * 384 + CH + h * HD) * HW;
    const __nv_bfloat16* KL = g_qkl + ((long)b * 384 + CH + h * HD) * HW;
    const uint32_t smb = smem_u32(gsm);

    // zero Q pad rows 24..31 (both stages, both planes)
    for (int i = tid; i < 2 * 2 * 8 * 68; i += 256) {
        int st = i / (2 * 8 * 68);
        int rem = i % (2 * 8 * 68);
        int pl = rem / (8 * 68);
        int r2 = rem % (8 * 68);
        gsm[st * GSTG + pl * 2176 + (24 + r2 / 68) * 68 + (r2 % 68)] = 0;
    }
    __syncthreads();

    auto load_tile = [&](int t, int st) {
        const long px = px0 + t * 128;
#pragma unroll
        for (int i = 0; i < 6; i++) {
            int slot = tid + i * 256;       // 0..1535
            int row = slot >> 4;            // 0..95
            int seg = slot & 15;            // 16B segment (8 bf16)
            int arr = row / 24;
            int ch  = row % 24;
            const __nv_bfloat16* src = (arr == 0) ? QH : (arr == 1) ? QL
                                     : (arr == 2) ? KH : KL;
            int off = (arr == 0) ? GQH : (arr == 1) ? GQL : (arr == 2) ? GKH : GKL;
            CP_ASYNC16(smb + (st * GSTG + off + ch * 68 + seg * 4) * 4,
                       src + (long)ch * HW + px + seg * 8);
        }
    };

    float acc[2][3][4];
#pragma unroll
    for (int mt = 0; mt < 2; mt++)
#pragma unroll
        for (int nt = 0; nt < 3; nt++)
#pragma unroll
            for (int i = 0; i < 4; i++) acc[mt][nt][i] = 0.f;

    load_tile(0, 0); CP_COMMIT();

    const int lrow = lane & 15, lcol = (lane >> 4) * 4;
    const int ws8 = wid * 8;   // this warp's 16-px k-step (8 u32)

    for (int t = 0; t < 16; t++) {
        const int st = t & 1;
        if (t + 1 < 16) { load_tile(t + 1, st ^ 1); CP_COMMIT(); CP_WAIT1(); }
        else { CP_WAIT0(); }
        __syncthreads();

        uint32_t qh[2][4], ql[2][4], kh[3][2], kl[3][2];
#pragma unroll
        for (int mt = 0; mt < 2; mt++) {
            uint32_t ro = smb + (st * GSTG + GQH + (mt * 16 + lrow) * 68 + lcol + ws8) * 4;
            ldsm_x4(qh[mt], ro);
            ldsm_x4(ql[mt], ro + (GQL - GQH) * 4);
        }
        {
            int g = lane >> 3;
            int rowB = (g >> 1) * 8 + (lane & 7);
            int segB = (g & 1) * 4;
            uint32_t roH = smb + (st * GSTG + GKH + rowB * 68 + segB + ws8) * 4;
            uint32_t r4[4];
            ldsm_x4(r4, roH);
            kh[0][0] = r4[0]; kh[0][1] = r4[1]; kh[1][0] = r4[2]; kh[1][1] = r4[3];
            ldsm_x4(r4, roH + (GKL - GKH) * 4);
            kl[0][0] = r4[0]; kl[0][1] = r4[1]; kl[1][0] = r4[2]; kl[1][1] = r4[3];
            int rowC = 16 + (lane & 7);
            int segC = ((lane >> 3) & 1) * 4;
            uint32_t roC = smb + (st * GSTG + GKH + rowC * 68 + segC + ws8) * 4;
            ldsm_x2(kh[2], roC);
            ldsm_x2(kl[2], roC + (GKL - GKH) * 4);
        }

#pragma unroll
        for (int mt = 0; mt < 2; mt++)
#pragma unroll
            for (int nt = 0; nt < 3; nt++)
                mma_bf16(acc[mt][nt], qh[mt], kh[nt]);
#pragma unroll
        for (int mt = 0; mt < 2; mt++)
#pragma unroll
            for (int nt = 0; nt < 3; nt++)
                mma_bf16(acc[mt][nt], qh[mt], kl[nt]);
#pragma unroll
        for (int mt = 0; mt < 2; mt++)
#pragma unroll
            for (int nt = 0; nt < 3; nt++)
                mma_bf16(acc[mt][nt], ql[mt], kh[nt]);
        __syncthreads();
    }

    // reduce 8 warps' partials via smem, atomicAdd into g_S
    float* red = reinterpret_cast<float*>(gsm);
#pragma unroll
    for (int mt = 0; mt < 2; mt++)
#pragma unroll
        for (int nt = 0; nt < 3; nt++)
#pragma unroll
            for (int rg = 0; rg < 4; rg++) {
                int m = mt * 16 + (lane >> 2) + (rg >> 1) * 8;
                int n = nt * 8 + (lane & 3) * 2 + (rg & 1);
                red[wid * 768 + m * 24 + n] = acc[mt][nt][rg];
            }
    __syncthreads();
    for (int o = tid; o < 576; o += 256) {
        float s = 0.f;
#pragma unroll
        for (int w = 0; w < 8; w++) s += red[w * 768 + o];
        atomicAdd(&g_S[(long)bh * 576 + o], s);
    }
}

// ---------------- normalize + softmax + fold attn into proj_w -> bf16 W ----------
__global__ __launch_bounds__(576) void combine_kernel(const float* __restrict__ proj_w,
                                                      const float* __restrict__ temp)
{
    const int bh = blockIdx.x;
    const int b = bh >> 3, h = bh & 7;
    __shared__ float attn[HD][HD];
    __shared__ float nq[HD], nk[HD];
    const int tid = threadIdx.x;
    if (tid < HD)
        nq[tid] = fmaxf(sqrtf(g_ssq[bh * HD + tid]), 1e-12f);
    else if (tid < 2 * HD)
        nk[tid - HD] = fmaxf(sqrtf(g_ssq[BATCH * HEADS * HD + bh * HD + (tid - HD)]), 1e-12f);
    __syncthreads();
    const float tv = temp[h];
    {
        int d = tid / HD, e = tid % HD;
        attn[d][e] = g_S[(long)bh * HD * HD + tid] / (nq[d] * nk[e]) * tv;
    }
    __syncthreads();
    if (tid < HD) {
        float m = -1e30f;
        for (int e = 0; e < HD; e++) m = fmaxf(m, attn[tid][e]);
        float sum = 0.f;
        for (int e = 0; e < HD; e++) { float v = expf(attn[tid][e] - m); attn[tid][e] = v; sum += v; }
        float inv = 1.f / sum;
        for (int e = 0; e < HD; e++) attn[tid][e] *= inv;
    }
    __syncthreads();
    for (int t = tid; t < CH * HD; t += 576) {
        int o = t / HD, e = t % HD;
        float a = 0.f;
#pragma unroll
        for (int d = 0; d < HD; d++)
            a += proj_w[o * CH + h * HD + d] * attn[d][e];
        __nv_bfloat16 hh, ll;
        split1(a, hh, ll);
        long idx = ((long)b * CH + o) * KDIM + h * HD + e;
        g_wbhi[idx] = hh;
        g_wblo[idx] = ll;
    }
}

// ---------------- launch ---------------------------------------------------------
extern "C" void kernel_launch(void* const* d_in, const int* in_sizes, int n_in,
                              void* d_out, int out_size)
{
    const float* x      = (const float*)d_in[0];
    const float* qkv_w  = (const float*)d_in[1];
    const float* dw_w   = (const float*)d_in[2];
    const float* proj_w = (const float*)d_in[3];
    const float* temp   = (const float*)d_in[4];
    float* out = (float*)d_out;

    float *p_qkv;
    __nv_bfloat16 *p_awhi, *p_awlo, *p_wbhi, *p_wblo;
    uint32_t *p_xphi, *p_xplo, *p_vphi, *p_vplo;
    cudaGetSymbolAddress((void**)&p_qkv,  g_qkv);
    cudaGetSymbolAddress((void**)&p_awhi, g_awhi);
    cudaGetSymbolAddress((void**)&p_awlo, g_awlo);
    cudaGetSymbolAddress((void**)&p_wbhi, g_wbhi);
    cudaGetSymbolAddress((void**)&p_wblo, g_wblo);
    cudaGetSymbolAddress((void**)&p_xphi, g_xphi);
    cudaGetSymbolAddress((void**)&p_xplo, g_xplo);
    cudaGetSymbolAddress((void**)&p_vphi, g_vphi);
    cudaGetSymbolAddress((void**)&p_vplo, g_vplo);

    cudaFuncSetAttribute(bf16_gemm_kernel,
                         cudaFuncAttributeMaxDynamicSharedMemorySize, SMEM_DYN_BYTES);
    cudaFuncSetAttribute(qk_gram_kernel,
                         cudaFuncAttributeMaxDynamicSharedMemorySize, GSM_BYTES);

    zero_kernel<<<72, 256>>>();
    split_x_kernel<<<dim3(64, KP, BATCH), 256>>>(x);
    split_aw_kernel<<<(576 * KDIM + 255) / 256, 256>>>(qkv_w);

    // 1) qkv = qkv_w @ x  (tensor cores, bf16 3-term split)
    bf16_gemm_kernel<<<dim3(9, HW / 128, BATCH), 256, SMEM_DYN_BYTES>>>(
        p_awhi, p_awlo, 0L, p_xphi, p_xplo, p_qkv, 576L * HW, 576);

    // 2) depthwise 3x3: q,k -> bf16 hi/lo planes (+sumsq), v -> packed pairs
    dwconv_kernel<<<dim3(IMG / 8, 480, BATCH), 256>>>(p_qkv, dw_w);

    // 3) gram via tensor cores
    qk_gram_kernel<<<dim3(32, HEADS, BATCH), 256, GSM_BYTES>>>();

    // 4) softmax + fold proj -> bf16 W planes
    combine_kernel<<<BATCH * HEADS, 576>>>(proj_w, temp);

    // 5) out = W[b] @ v  (tensor cores, bf16 3-term split)
    bf16_gemm_kernel<<<dim3(3, HW / 128, BATCH), 256, SMEM_DYN_BYTES>>>(
        p_wbhi, p_wblo, (long)CH * KDIM, p_vphi, p_vplo, out, (long)CH * HW, CH);
}

// round 14
// speedup vs baseline: 1.4468x; 1.4468x over previous
#include <cuda_runtime.h>
#include <cuda_bf16.h>
#include <math.h>
#include <stdint.h>

#define HW    65536
#define IMG   256
#define BATCH 4
#define CH    192
#define HEADS 8
#define HD    24
#define KDIM  192
#define KP    96      // k pairs
#define KITER 6       // K=32 chunks

// ---------------- scratch (device globals; no runtime allocation) ----------------
__device__ float    g_qkv [(long)BATCH * 576 * HW];   // after 1x1 conv (fp32)
__device__ __nv_bfloat16 g_qkh[(long)BATCH * 384 * HW];  // q,k after dw, bf16 hi
__device__ __nv_bfloat16 g_qkl[(long)BATCH * 384 * HW];  // q,k after dw, bf16 lo
__device__ uint32_t g_xphi[(long)BATCH * KP * HW];    // x packed bf16 k-pairs, hi
__device__ uint32_t g_xplo[(long)BATCH * KP * HW];    // lo
__device__ uint32_t g_vphi[(long)BATCH * KP * HW];    // v packed bf16 k-pairs, hi
__device__ uint32_t g_vplo[(long)BATCH * KP * HW];
__device__ __nv_bfloat16 g_awhi[576 * KDIM];          // qkv_w bf16 hi
__device__ __nv_bfloat16 g_awlo[576 * KDIM];
__device__ __nv_bfloat16 g_wbhi[BATCH * CH * KDIM];   // folded proj W bf16 hi
__device__ __nv_bfloat16 g_wblo[BATCH * CH * KDIM];
__device__ float g_S  [BATCH * HEADS * HD * HD];
__device__ float g_ssq[2 * BATCH * HEADS * HD];

// ---------------- helpers ---------------------------------------------------------
__device__ __forceinline__ void split1(float v, __nv_bfloat16& h, __nv_bfloat16& l)
{
    h = __float2bfloat16(v);
    l = __float2bfloat16(v - __bfloat162float(h));
}
__device__ __forceinline__ uint32_t smem_u32(const void* p)
{
    uint32_t a;
    asm("{ .reg .u64 t; cvta.to.shared.u64 t, %1; cvt.u32.u64 %0, t; }" : "=r"(a) : "l"(p));
    return a;
}
__device__ __forceinline__ void mma_bf16(float* d, const uint32_t* a, const uint32_t* b)
{
    asm volatile(
        "mma.sync.aligned.m16n8k16.row.col.f32.bf16.bf16.f32 "
        "{%0,%1,%2,%3}, {%4,%5,%6,%7}, {%8,%9}, {%0,%1,%2,%3};\n"
        : "+f"(d[0]), "+f"(d[1]), "+f"(d[2]), "+f"(d[3])
        : "r"(a[0]), "r"(a[1]), "r"(a[2]), "r"(a[3]), "r"(b[0]), "r"(b[1]));
}
__device__ __forceinline__ void ldsm_x4(uint32_t* r, uint32_t addr)
{
    asm volatile("ldmatrix.sync.aligned.m8n8.x4.shared.b16 {%0,%1,%2,%3}, [%4];"
                 : "=r"(r[0]), "=r"(r[1]), "=r"(r[2]), "=r"(r[3]) : "r"(addr));
}
__device__ __forceinline__ void ldsm_x2(uint32_t* r, uint32_t addr)
{
    asm volatile("ldmatrix.sync.aligned.m8n8.x2.shared.b16 {%0,%1}, [%2];"
                 : "=r"(r[0]), "=r"(r[1]) : "r"(addr));
}
#define CP_ASYNC16(saddr, gptr) \
    asm volatile("cp.async.cg.shared.global [%0], [%1], 16;" :: "r"(saddr), "l"(gptr))
#define CP_COMMIT()  asm volatile("cp.async.commit_group;" ::: "memory")
#define CP_WAIT0()   asm volatile("cp.async.wait_group 0;" ::: "memory")
#define CP_WAIT1()   asm volatile("cp.async.wait_group 1;" ::: "memory")

// main GEMM smem (u32 units)
#define A_PLANE(st, p) (((st) * 2 + (p)) * 64 * 20)
#define B_PLANE(st, p) (7680 + ((st) * 2 + (p)) * 16 * 136)
#define SMEM_DYN_BYTES ((7680 + 3 * 2 * 16 * 136) * 4)   // 82944 B

// gram smem (u32 units)
#define GQH 0
#define GQL 2176
#define GKH 4352
#define GKL 5984
#define GSTG 7616
#define GSM_BYTES (2 * GSTG * 4)   // 60928 B

// ---------------- zero accumulators ----------------------------------------------
__global__ void zero_kernel()
{
    int i = blockIdx.x * blockDim.x + threadIdx.x;
    if (i < BATCH * HEADS * HD * HD) g_S[i] = 0.f;
    if (i < 2 * BATCH * HEADS * HD)  g_ssq[i] = 0.f;
}

// ---------------- split x -> packed bf16 k-pair planes ----------------------------
__global__ __launch_bounds__(256) void split_x_kernel(const float* __restrict__ x)
{
    const int n = (blockIdx.x * 256 + threadIdx.x) * 4;
    const int j = blockIdx.y;
    const int b = blockIdx.z;
    const float* r0 = x + ((long)b * KDIM + 2 * j) * HW + n;
    float4 v0 = *reinterpret_cast<const float4*>(r0);
    float4 v1 = *reinterpret_cast<const float4*>(r0 + HW);
    float e[4] = {v0.x, v0.y, v0.z, v0.w};
    float o[4] = {v1.x, v1.y, v1.z, v1.w};
    uint4 hi, lo;
    uint32_t* hp = &hi.x; uint32_t* lp = &lo.x;
#pragma unroll
    for (int i = 0; i < 4; i++) {
        __nv_bfloat16 eh, el, oh, ol;
        split1(e[i], eh, el);
        split1(o[i], oh, ol);
        hp[i] = (uint32_t)*reinterpret_cast<unsigned short*>(&eh) |
                ((uint32_t)*reinterpret_cast<unsigned short*>(&oh) << 16);
        lp[i] = (uint32_t)*reinterpret_cast<unsigned short*>(&el) |
                ((uint32_t)*reinterpret_cast<unsigned short*>(&ol) << 16);
    }
    const long w = ((long)b * KP + j) * HW + n;
    *reinterpret_cast<uint4*>(&g_xphi[w]) = hi;
    *reinterpret_cast<uint4*>(&g_xplo[w]) = lo;
}

// ---------------- split qkv_w -> bf16 hi/lo planes --------------------------------
__global__ void split_aw_kernel(const float* __restrict__ qkv_w)
{
    int i = blockIdx.x * 256 + threadIdx.x;
    if (i < 576 * KDIM) {
        __nv_bfloat16 h, l;
        split1(qkv_w[i], h, l);
        g_awhi[i] = h; g_awlo[i] = l;
    }
}

// ---------------- bf16 split GEMM (unchanged) -------------------------------------
__global__ __launch_bounds__(256) void bf16_gemm_kernel(
    const __nv_bfloat16* __restrict__ Ahi, const __nv_bfloat16* __restrict__ Alo, long aStride,
    const uint32_t* __restrict__ Bhi, const uint32_t* __restrict__ Blo,
    float* __restrict__ C, long cStride, int M)
{
    extern __shared__ uint32_t sm[];
    const uint32_t smb = smem_u32(sm);

    const int tid  = threadIdx.x;
    const int lane = tid & 31;
    const int wid  = tid >> 5;
    const int bm   = blockIdx.x * 64;
    const long n0  = (long)blockIdx.y * 128;
    const int bz   = blockIdx.z;

    const __nv_bfloat16* Ah = Ahi + (long)bz * aStride;
    const __nv_bfloat16* Al = Alo + (long)bz * aStride;
    const uint32_t* Bh = Bhi + (long)bz * KP * HW;
    const uint32_t* Bl = Blo + (long)bz * KP * HW;
    float* Cb = C + (long)bz * cStride;

    const int warp_m = (wid & 1) * 32;
    const int warp_n = (wid >> 1) * 32;
    const int r  = lane >> 2;
    const int cq = lane & 3;
    const int lrow = lane & 15;
    const int lcol = (lane >> 4) * 4;

    float acc[2][4][4];
#pragma unroll
    for (int mt = 0; mt < 2; mt++)
#pragma unroll
        for (int nt = 0; nt < 4; nt++)
#pragma unroll
            for (int i = 0; i < 4; i++) acc[mt][nt][i] = 0.f;

    auto load_chunk = [&](int c, int st) {
        {
            int m = tid >> 2, kg = tid & 3;
            long ge = (long)(bm + m) * KDIM + c * 32 + kg * 8;
            CP_ASYNC16(smb + (A_PLANE(st, 0) + m * 20 + kg * 4) * 4, (const char*)Ah + ge * 2);
            CP_ASYNC16(smb + (A_PLANE(st, 1) + m * 20 + kg * 4) * 4, (const char*)Al + ge * 2);
        }
#pragma unroll
        for (int i = 0; i < 2; i++) {
            int slot = tid + i * 256;
            int j = slot >> 5, ln = slot & 31;
            long gw = ((long)(c * 16 + j)) * HW + n0 + 4 * ln;
            CP_ASYNC16(smb + (B_PLANE(st, 0) + j * 136 + 4 * ln) * 4, Bh + gw);
            CP_ASYNC16(smb + (B_PLANE(st, 1) + j * 136 + 4 * ln) * 4, Bl + gw);
        }
    };

    load_chunk(0, 0); CP_COMMIT();
    load_chunk(1, 1); CP_COMMIT();

    for (int c = 0; c < KITER; c++) {
        const int st = c % 3;
        if (c == KITER - 1) { CP_WAIT0(); } else { CP_WAIT1(); }
        __syncthreads();

        const uint32_t baseHi = smb + A_PLANE(st, 0) * 4;
        const uint32_t baseLo = smb + A_PLANE(st, 1) * 4;
        const uint32_t* BsH = sm + B_PLANE(st, 0);
        const uint32_t* BsL = sm + B_PLANE(st, 1);

#pragma unroll
        for (int ksub = 0; ksub < 2; ksub++) {
            uint32_t ah[2][4], al[2][4], bh[4][2], bl[4][2];
#pragma unroll
            for (int mt = 0; mt < 2; mt++) {
                const uint32_t roff = ((warp_m + mt * 16 + lrow) * 20 + lcol + ksub * 8) * 4;
                ldsm_x4(ah[mt], baseHi + roff);
                ldsm_x4(al[mt], baseLo + roff);
            }
            const int kp0 = ksub * 8;
#pragma unroll
            for (int nt = 0; nt < 4; nt++) {
                const int n = warp_n + nt * 8 + r;
                bh[nt][0] = BsH[(kp0 + cq) * 136 + n];
                bh[nt][1] = BsH[(kp0 + cq + 4) * 136 + n];
                bl[nt][0] = BsL[(kp0 + cq) * 136 + n];
                bl[nt][1] = BsL[(kp0 + cq + 4) * 136 + n];
            }

            if (ksub == 0 && c + 2 < KITER) {
                load_chunk(c + 2, (c + 2) % 3);
                CP_COMMIT();
            }

#pragma unroll
            for (int mt = 0; mt < 2; mt++)
#pragma unroll
                for (int nt = 0; nt < 4; nt++)
                    mma_bf16(acc[mt][nt], ah[mt], bh[nt]);
#pragma unroll
            for (int mt = 0; mt < 2; mt++)
#pragma unroll
                for (int nt = 0; nt < 4; nt++)
                    mma_bf16(acc[mt][nt], ah[mt], bl[nt]);
#pragma unroll
            for (int mt = 0; mt < 2; mt++)
#pragma unroll
                for (int nt = 0; nt < 4; nt++)
                    mma_bf16(acc[mt][nt], al[mt], bh[nt]);
        }
    }

#pragma unroll
    for (int mt = 0; mt < 2; mt++)
#pragma unroll
        for (int nt = 0; nt < 4; nt++) {
            const int row = bm + warp_m + mt * 16 + r;
            const long col = n0 + warp_n + nt * 8 + 2 * cq;
            *reinterpret_cast<float2*>(Cb + (long)row * HW + col) =
                make_float2(acc[mt][nt][0], acc[mt][nt][1]);
            *reinterpret_cast<float2*>(Cb + (long)(row + 8) * HW + col) =
                make_float2(acc[mt][nt][2], acc[mt][nt][3]);
        }
}

// ---------------- depthwise 3x3: q,k -> bf16 hi/lo (+sumsq); v -> packed pairs ----
__global__ __launch_bounds__(256) void dwconv_kernel(const float* __restrict__ in,
                                                     const float* __restrict__ w)
{
    const int y = blockIdx.y;     // 0..383 single q/k channel; 384..479 v pair
    const int b = blockIdx.z;
    const int t = threadIdx.x;
    const int r0 = blockIdx.x * 8;

    __shared__ float s[10][258];

    if (y < 384) {
        const int ch = y;
        const float* ip = in + ((long)b * 576 + ch) * HW;
        __nv_bfloat16* oh = g_qkh + ((long)b * 384 + ch) * HW;
        __nv_bfloat16* ol = g_qkl + ((long)b * 384 + ch) * HW;
        float w9[9];
#pragma unroll
        for (int i = 0; i < 9; i++) w9[i] = __ldg(&w[ch * 9 + i]);
#pragma unroll
        for (int rr = 0; rr < 10; rr++) {
            int rw = r0 - 1 + rr;
            s[rr][t + 1] = (rw >= 0 && rw < IMG) ? ip[rw * IMG + t] : 0.f;
        }
        if (t < 10) { s[t][0] = 0.f; s[t][257] = 0.f; }
        __syncthreads();
        float sq = 0.f;
#pragma unroll
        for (int rr = 0; rr < 8; rr++) {
            float a = 0.f;
#pragma unroll
            for (int ky = 0; ky < 3; ky++)
#pragma unroll
                for (int kx = 0; kx < 3; kx++)
                    a += s[rr + ky][t + kx] * w9[ky * 3 + kx];
            __nv_bfloat16 hh, ll;
            split1(a, hh, ll);
            oh[(r0 + rr) * IMG + t] = hh;
            ol[(r0 + rr) * IMG + t] = ll;
            sq += a * a;
        }
        __shared__ float wsum[8];
#pragma unroll
        for (int off = 16; off > 0; off >>= 1)
            sq += __shfl_xor_sync(0xFFFFFFFFu, sq, off);
        if ((t & 31) == 0) wsum[t >> 5] = sq;
        __syncthreads();
        if (t == 0) {
            float ssum = 0.f;
#pragma unroll
            for (int i = 0; i < 8; i++) ssum += wsum[i];
            int off = (ch < CH) ? (b * CH + ch)
                                : (BATCH * HEADS * HD + b * CH + (ch - CH));
            atomicAdd(&g_ssq[off], ssum);
        }
    } else {
        const int p = y - 384;             // v channel pair
        const int ch0 = 384 + 2 * p;
        float ce[8], co[8];
#pragma unroll
        for (int cc = 0; cc < 2; cc++) {
            const int ch = ch0 + cc;
            const float* ip = in + ((long)b * 576 + ch) * HW;
            float w9[9];
#pragma unroll
            for (int i = 0; i < 9; i++) w9[i] = __ldg(&w[ch * 9 + i]);
            __syncthreads();
#pragma unroll
            for (int rr = 0; rr < 10; rr++) {
                int rw = r0 - 1 + rr;
                s[rr][t + 1] = (rw >= 0 && rw < IMG) ? ip[rw * IMG + t] : 0.f;
            }
            if (t < 10) { s[t][0] = 0.f; s[t][257] = 0.f; }
            __syncthreads();
            float* dst = cc ? co : ce;
#pragma unroll
            for (int rr = 0; rr < 8; rr++) {
                float a = 0.f;
#pragma unroll
                for (int ky = 0; ky < 3; ky++)
#pragma unroll
                    for (int kx = 0; kx < 3; kx++)
                        a += s[rr + ky][t + kx] * w9[ky * 3 + kx];
                dst[rr] = a;
            }
        }
        const long vbase = ((long)b * KP + p) * HW;
#pragma unroll
        for (int rr = 0; rr < 8; rr++) {
            __nv_bfloat16 eh, el, oh2, ol2;
            split1(ce[rr], eh, el);
            split1(co[rr], oh2, ol2);
            uint32_t hw_ = (uint32_t)*reinterpret_cast<unsigned short*>(&eh) |
                           ((uint32_t)*reinterpret_cast<unsigned short*>(&oh2) << 16);
            uint32_t lw_ = (uint32_t)*reinterpret_cast<unsigned short*>(&el) |
                           ((uint32_t)*reinterpret_cast<unsigned short*>(&ol2) << 16);
            g_vphi[vbase + (r0 + rr) * IMG + t] = hw_;
            g_vplo[vbase + (r0 + rr) * IMG + t] = lw_;
        }
    }
}

// ---------------- gram via tensor cores: S[24x24] = q k^T per (b,h) --------------
__global__ __launch_bounds__(256) void qk_gram_kernel()
{
    extern __shared__ uint32_t gsm[];
    const int tid = threadIdx.x, lane = tid & 31, wid = tid >> 5;
    const int b = blockIdx.z, h = blockIdx.y;
    const int bh = b * HEADS + h;
    const long px0 = (long)blockIdx.x * 2048;
    const __nv_bfloat16* QH = g_qkh + ((long)b * 384 + h * HD) * HW;
    const __nv_bfloat16* QL = g_qkl + ((long)b * 384 + h * HD) * HW;
    const __nv_bfloat16* KH = g_qkh + ((long)b * 384 + CH + h * HD) * HW;
    const __nv_bfloat16* KL = g_qkl + ((long)b * 384 + CH + h * HD) * HW;
    const uint32_t smb = smem_u32(gsm);

    // zero Q pad rows 24..31 (both stages, both planes)
    for (int i = tid; i < 2 * 2 * 8 * 68; i += 256) {
        int st = i / (2 * 8 * 68);
        int rem = i % (2 * 8 * 68);
        int pl = rem / (8 * 68);
        int r2 = rem % (8 * 68);
        gsm[st * GSTG + pl * 2176 + (24 + r2 / 68) * 68 + (r2 % 68)] = 0;
    }
    __syncthreads();

    auto load_tile = [&](int t, int st) {
        const long px = px0 + t * 128;
#pragma unroll
        for (int i = 0; i < 6; i++) {
            int slot = tid + i * 256;       // 0..1535
            int row = slot >> 4;            // 0..95
            int seg = slot & 15;            // 16B segment (8 bf16)
            int arr = row / 24;
            int ch  = row % 24;
            const __nv_bfloat16* src = (arr == 0) ? QH : (arr == 1) ? QL
                                     : (arr == 2) ? KH : KL;
            int off = (arr == 0) ? GQH : (arr == 1) ? GQL : (arr == 2) ? GKH : GKL;
            CP_ASYNC16(smb + (st * GSTG + off + ch * 68 + seg * 4) * 4,
                       src + (long)ch * HW + px + seg * 8);
        }
    };

    float acc[2][3][4];
#pragma unroll
    for (int mt = 0; mt < 2; mt++)
#pragma unroll
        for (int nt = 0; nt < 3; nt++)
#pragma unroll
            for (int i = 0; i < 4; i++) acc[mt][nt][i] = 0.f;

    load_tile(0, 0); CP_COMMIT();

    const int lrow = lane & 15, lcol = (lane >> 4) * 4;
    const int ws8 = wid * 8;   // this warp's 16-px k-step (8 u32)

    for (int t = 0; t < 16; t++) {
        const int st = t & 1;
        if (t + 1 < 16) { load_tile(t + 1, st ^ 1); CP_COMMIT(); CP_WAIT1(); }
        else { CP_WAIT0(); }
        __syncthreads();

        uint32_t qh[2][4], ql[2][4], kh[3][2], kl[3][2];
#pragma unroll
        for (int mt = 0; mt < 2; mt++) {
            uint32_t ro = smb + (st * GSTG + GQH + (mt * 16 + lrow) * 68 + lcol + ws8) * 4;
            ldsm_x4(qh[mt], ro);
            ldsm_x4(ql[mt], ro + (GQL - GQH) * 4);
        }
        {
            int g = lane >> 3;
            int rowB = (g >> 1) * 8 + (lane & 7);
            int segB = (g & 1) * 4;
            uint32_t roH = smb + (st * GSTG + GKH + rowB * 68 + segB + ws8) * 4;
            uint32_t r4[4];
            ldsm_x4(r4, roH);
            kh[0][0] = r4[0]; kh[0][1] = r4[1]; kh[1][0] = r4[2]; kh[1][1] = r4[3];
            ldsm_x4(r4, roH + (GKL - GKH) * 4);
            kl[0][0] = r4[0]; kl[0][1] = r4[1]; kl[1][0] = r4[2]; kl[1][1] = r4[3];
            int rowC = 16 + (lane & 7);
            int segC = ((lane >> 3) & 1) * 4;
            uint32_t roC = smb + (st * GSTG + GKH + rowC * 68 + segC + ws8) * 4;
            ldsm_x2(kh[2], roC);
            ldsm_x2(kl[2], roC + (GKL - GKH) * 4);
        }

#pragma unroll
        for (int mt = 0; mt < 2; mt++)
#pragma unroll
            for (int nt = 0; nt < 3; nt++)
                mma_bf16(acc[mt][nt], qh[mt], kh[nt]);
#pragma unroll
        for (int mt = 0; mt < 2; mt++)
#pragma unroll
            for (int nt = 0; nt < 3; nt++)
                mma_bf16(acc[mt][nt], qh[mt], kl[nt]);
#pragma unroll
        for (int mt = 0; mt < 2; mt++)
#pragma unroll
            for (int nt = 0; nt < 3; nt++)
                mma_bf16(acc[mt][nt], ql[mt], kh[nt]);
        __syncthreads();
    }

    // reduce 8 warps' partials via smem, atomicAdd into g_S
    float* red = reinterpret_cast<float*>(gsm);
#pragma unroll
    for (int mt = 0; mt < 2; mt++)
#pragma unroll
        for (int nt = 0; nt < 3; nt++)
#pragma unroll
            for (int rg = 0; rg < 4; rg++) {
                int m = mt * 16 + (lane >> 2) + (rg >> 1) * 8;
                int n = nt * 8 + (lane & 3) * 2 + (rg & 1);
                red[wid * 768 + m * 24 + n] = acc[mt][nt][rg];
            }
    __syncthreads();
    for (int o = tid; o < 576; o += 256) {
        float s = 0.f;
#pragma unroll
        for (int w = 0; w < 8; w++) s += red[w * 768 + o];
        atomicAdd(&g_S[(long)bh * 576 + o], s);
    }
}

// ---------------- normalize + softmax + fold attn into proj_w -> bf16 W ----------
__global__ __launch_bounds__(576) void combine_kernel(const float* __restrict__ proj_w,
                                                      const float* __restrict__ temp)
{
    const int bh = blockIdx.x;
    const int b = bh >> 3, h = bh & 7;
    __shared__ float attn[HD][HD];
    __shared__ float nq[HD], nk[HD];
    const int tid = threadIdx.x;
    if (tid < HD)
        nq[tid] = fmaxf(sqrtf(g_ssq[bh * HD + tid]), 1e-12f);
    else if (tid < 2 * HD)
        nk[tid - HD] = fmaxf(sqrtf(g_ssq[BATCH * HEADS * HD + bh * HD + (tid - HD)]), 1e-12f);
    __syncthreads();
    const float tv = temp[h];
    {
        int d = tid / HD, e = tid % HD;
        attn[d][e] = g_S[(long)bh * HD * HD + tid] / (nq[d] * nk[e]) * tv;
    }
    __syncthreads();
    if (tid < HD) {
        float m = -1e30f;
        for (int e = 0; e < HD; e++) m = fmaxf(m, attn[tid][e]);
        float sum = 0.f;
        for (int e = 0; e < HD; e++) { float v = expf(attn[tid][e] - m); attn[tid][e] = v; sum += v; }
        float inv = 1.f / sum;
        for (int e = 0; e < HD; e++) attn[tid][e] *= inv;
    }
    __syncthreads();
    for (int t = tid; t < CH * HD; t += 576) {
        int o = t / HD, e = t % HD;
        float a = 0.f;
#pragma unroll
        for (int d = 0; d < HD; d++)
            a += proj_w[o * CH + h * HD + d] * attn[d][e];
        __nv_bfloat16 hh, ll;
        split1(a, hh, ll);
        long idx = ((long)b * CH + o) * KDIM + h * HD + e;
        g_wbhi[idx] = hh;
        g_wblo[idx] = ll;
    }
}

// ---------------- launch ---------------------------------------------------------
extern "C" void kernel_launch(void* const* d_in, const int* in_sizes, int n_in,
                              void* d_out, int out_size)
{
    const float* x      = (const float*)d_in[0];
    const float* qkv_w  = (const float*)d_in[1];
    const float* dw_w   = (const float*)d_in[2];
    const float* proj_w = (const float*)d_in[3];
    const float* temp   = (const float*)d_in[4];
    float* out = (float*)d_out;

    float *p_qkv;
    __nv_bfloat16 *p_awhi, *p_awlo, *p_wbhi, *p_wblo;
    uint32_t *p_xphi, *p_xplo, *p_vphi, *p_vplo;
    cudaGetSymbolAddress((void**)&p_qkv,  g_qkv);
    cudaGetSymbolAddress((void**)&p_awhi, g_awhi);
    cudaGetSymbolAddress((void**)&p_awlo, g_awlo);
    cudaGetSymbolAddress((void**)&p_wbhi, g_wbhi);
    cudaGetSymbolAddress((void**)&p_wblo, g_wblo);
    cudaGetSymbolAddress((void**)&p_xphi, g_xphi);
    cudaGetSymbolAddress((void**)&p_xplo, g_xplo);
    cudaGetSymbolAddress((void**)&p_vphi, g_vphi);
    cudaGetSymbolAddress((void**)&p_vplo, g_vplo);

    cudaFuncSetAttribute(bf16_gemm_kernel,
                         cudaFuncAttributeMaxDynamicSharedMemorySize, SMEM_DYN_BYTES);
    cudaFuncSetAttribute(qk_gram_kernel,
                         cudaFuncAttributeMaxDynamicSharedMemorySize, GSM_BYTES);

    zero_kernel<<<72, 256>>>();
    split_x_kernel<<<dim3(64, KP, BATCH), 256>>>(x);
    split_aw_kernel<<<(576 * KDIM + 255) / 256, 256>>>(qkv_w);

    // 1) qkv = qkv_w @ x  (tensor cores, bf16 3-term split)
    bf16_gemm_kernel<<<dim3(9, HW / 128, BATCH), 256, SMEM_DYN_BYTES>>>(
        p_awhi, p_awlo, 0L, p_xphi, p_xplo, p_qkv, 576L * HW, 576);

    // 2) depthwise 3x3: q,k -> bf16 hi/lo planes (+sumsq), v -> packed pairs
    dwconv_kernel<<<dim3(IMG / 8, 480, BATCH), 256>>>(p_qkv, dw_w);

    // 3) gram via tensor cores
    qk_gram_kernel<<<dim3(32, HEADS, BATCH), 256, GSM_BYTES>>>();

    // 4) softmax + fold proj -> bf16 W planes
    combine_kernel<<<BATCH * HEADS, 576>>>(proj_w, temp);

    // 5) out = W[b] @ v  (tensor cores, bf16 3-term split)
    bf16_gemm_kernel<<<dim3(3, HW / 128, BATCH), 256, SMEM_DYN_BYTES>>>(
        p_wbhi, p_wblo, (long)CH * KDIM, p_vphi, p_vplo, out, (long)CH * HW, CH);
}